// round 1
// baseline (speedup 1.0000x reference)
#include <cuda_runtime.h>
#include <math.h>

// Problem constants
#define Bn   2
#define Tn   2048
#define Dn   2048
#define Hn   16
#define Gn   4
#define HD   128
#define DKV  512
#define MROWS (Bn * Tn)   // 4096

// Scratch (allocation-free: __device__ globals)
__device__ float g_Q[(size_t)MROWS * Dn];   // 32 MB
__device__ float g_K[(size_t)MROWS * DKV];  // 8 MB
__device__ float g_V[(size_t)MROWS * DKV];  // 8 MB
__device__ float g_A[(size_t)MROWS * Dn];   // 32 MB (attention output)

// ---------------------------------------------------------------------------
// SGEMM: C[M,N] = A[M,K] @ B[K,N], all row-major fp32.
// 128x128 block tile, TK=16, 256 threads, 8x8 register tile per thread.
// Requires M%128==0, N%128==0, K%16==0 (true for all 4 calls).
// ---------------------------------------------------------------------------
__global__ __launch_bounds__(256) void sgemm128(
    const float* __restrict__ A, const float* __restrict__ B,
    float* __restrict__ C, int M, int N, int K)
{
    __shared__ float As[16 * 128];  // [k][m]
    __shared__ float Bs[16 * 128];  // [k][n]

    const int tid = threadIdx.x;
    const int tx = tid & 15;        // 0..15 -> n sub-tile
    const int ty = tid >> 4;        // 0..15 -> m sub-tile
    const int row0 = blockIdx.y * 128;
    const int col0 = blockIdx.x * 128;

    float acc[8][8];
#pragma unroll
    for (int i = 0; i < 8; i++)
#pragma unroll
        for (int j = 0; j < 8; j++) acc[i][j] = 0.f;

    for (int k0 = 0; k0 < K; k0 += 16) {
        // Load A tile (128 rows x 16 k) -> As[k][m] (transposed store)
#pragma unroll
        for (int i = 0; i < 2; i++) {
            int idx = tid + i * 256;          // 0..511 float4 units
            int r  = idx >> 2;                // 0..127
            int c4 = idx & 3;                 // 0..3
            float4 v = *(const float4*)(A + (size_t)(row0 + r) * K + k0 + c4 * 4);
            As[(c4 * 4 + 0) * 128 + r] = v.x;
            As[(c4 * 4 + 1) * 128 + r] = v.y;
            As[(c4 * 4 + 2) * 128 + r] = v.z;
            As[(c4 * 4 + 3) * 128 + r] = v.w;
        }
        // Load B tile (16 k x 128 cols) -> Bs[k][n]
#pragma unroll
        for (int i = 0; i < 2; i++) {
            int idx = tid + i * 256;
            int r  = idx >> 5;                // 0..15
            int c4 = idx & 31;                // 0..31
            *(float4*)(Bs + r * 128 + c4 * 4) =
                *(const float4*)(B + (size_t)(k0 + r) * N + col0 + c4 * 4);
        }
        __syncthreads();

#pragma unroll
        for (int kk = 0; kk < 16; kk++) {
            float a[8], b[8];
            *(float4*)&a[0] = *(float4*)(As + kk * 128 + ty * 8);
            *(float4*)&a[4] = *(float4*)(As + kk * 128 + ty * 8 + 4);
            *(float4*)&b[0] = *(float4*)(Bs + kk * 128 + tx * 8);
            *(float4*)&b[4] = *(float4*)(Bs + kk * 128 + tx * 8 + 4);
#pragma unroll
            for (int i = 0; i < 8; i++)
#pragma unroll
                for (int j = 0; j < 8; j++)
                    acc[i][j] += a[i] * b[j];
        }
        __syncthreads();
    }

#pragma unroll
    for (int i = 0; i < 8; i++) {
        float* cp = C + (size_t)(row0 + ty * 8 + i) * N + col0 + tx * 8;
        *(float4*)(cp)     = make_float4(acc[i][0], acc[i][1], acc[i][2], acc[i][3]);
        *(float4*)(cp + 4) = make_float4(acc[i][4], acc[i][5], acc[i][6], acc[i][7]);
    }
}

// ---------------------------------------------------------------------------
// Flash attention (causal, GQA), fp32, online softmax.
// Block: 256 threads handles one 64-row query tile of one head (b,h).
// BQ = BK = 64, head_dim = 128.
// Layouts:
//   sQ  [64][128]  (pre-scaled by 1/sqrt(hd))
//   sK  [64][132]  (padded to 132 floats/row -> 2-way max conflict on reads)
//   sV  [64][128]
//   sP  [64][64]
// Score phase: thread (tx,ty) owns S rows 4ty..+3, cols 4tx..+3.
// PV/output:   thread (tx,ty) owns O rows 4ty..+3, cols 8tx..+7.
// ---------------------------------------------------------------------------
#define ATTN_SMEM ((64*128 + 64*132 + 64*128 + 64*64) * 4)   // 115712 B

__global__ __launch_bounds__(256) void attn_kernel()
{
    extern __shared__ float sm[];
    float* sQ = sm;                    // 8192
    float* sK = sQ + 64 * 128;         // 8448 (padded rows of 132)
    float* sV = sK + 64 * 132;         // 8192
    float* sP = sV + 64 * 128;         // 4096

    const int qt  = blockIdx.x;        // query tile 0..31
    const int bh  = blockIdx.y;        // 0..31
    const int b   = bh >> 4;
    const int h   = bh & 15;
    const int g   = h >> 2;            // kv head
    const int tid = threadIdx.x;
    const int tx  = tid & 15;
    const int ty  = tid >> 4;
    const int q0  = qt * 64;
    const float scale = 0.08838834764831843f;  // 1/sqrt(128)

    // Load Q tile, pre-scaled
    {
        const float* qsrc = g_Q + (size_t)(b * Tn + q0) * Dn + h * HD;
#pragma unroll
        for (int i = 0; i < 8; i++) {
            int idx = tid + i * 256;
            int r  = idx >> 5;         // 0..63
            int c4 = idx & 31;         // 0..31
            float4 v = *(const float4*)(qsrc + (size_t)r * Dn + c4 * 4);
            v.x *= scale; v.y *= scale; v.z *= scale; v.w *= scale;
            *(float4*)(sQ + r * 128 + c4 * 4) = v;
        }
    }

    float m_r[4], l_r[4], acc[4][8];
#pragma unroll
    for (int i = 0; i < 4; i++) {
        m_r[i] = -INFINITY; l_r[i] = 0.f;
#pragma unroll
        for (int j = 0; j < 8; j++) acc[i][j] = 0.f;
    }

    const float* ksrc0 = g_K + (size_t)(b * Tn) * DKV + g * HD;
    const float* vsrc0 = g_V + (size_t)(b * Tn) * DKV + g * HD;

    for (int kt = 0; kt <= qt; kt++) {
        __syncthreads();   // prior PV done (and first iter: sQ visible)

        // Load K (into padded rows) and V
        {
            const float* ks = ksrc0 + (size_t)(kt * 64) * DKV;
            const float* vs = vsrc0 + (size_t)(kt * 64) * DKV;
#pragma unroll
            for (int i = 0; i < 8; i++) {
                int idx = tid + i * 256;
                int r  = idx >> 5;
                int c4 = idx & 31;
                *(float4*)(sK + r * 132 + c4 * 4) =
                    *(const float4*)(ks + (size_t)r * DKV + c4 * 4);
                *(float4*)(sV + r * 128 + c4 * 4) =
                    *(const float4*)(vs + (size_t)r * DKV + c4 * 4);
            }
        }
        __syncthreads();

        // Scores: s[i][j] = dot(Q[4ty+i], K[4tx+j]) over d=0..127
        float s[4][4];
#pragma unroll
        for (int i = 0; i < 4; i++)
#pragma unroll
            for (int j = 0; j < 4; j++) s[i][j] = 0.f;

#pragma unroll 8
        for (int d4 = 0; d4 < 128; d4 += 4) {
            float4 a[4], bv[4];
#pragma unroll
            for (int i = 0; i < 4; i++)
                a[i] = *(float4*)(sQ + (4 * ty + i) * 128 + d4);
#pragma unroll
            for (int j = 0; j < 4; j++)
                bv[j] = *(float4*)(sK + (4 * tx + j) * 132 + d4);
#pragma unroll
            for (int i = 0; i < 4; i++)
#pragma unroll
                for (int j = 0; j < 4; j++)
                    s[i][j] += a[i].x * bv[j].x + a[i].y * bv[j].y
                             + a[i].z * bv[j].z + a[i].w * bv[j].w;
        }

        const bool diag = (kt == qt);

        // Online softmax per row (rows 4ty+i shared by the 16 tx lanes)
#pragma unroll
        for (int i = 0; i < 4; i++) {
            const int row = 4 * ty + i;
            if (diag) {
#pragma unroll
                for (int j = 0; j < 4; j++)
                    if (4 * tx + j > row) s[i][j] = -INFINITY;
            }
            float mm = fmaxf(fmaxf(s[i][0], s[i][1]), fmaxf(s[i][2], s[i][3]));
            mm = fmaxf(mm, __shfl_xor_sync(0xffffffffu, mm, 1));
            mm = fmaxf(mm, __shfl_xor_sync(0xffffffffu, mm, 2));
            mm = fmaxf(mm, __shfl_xor_sync(0xffffffffu, mm, 4));
            mm = fmaxf(mm, __shfl_xor_sync(0xffffffffu, mm, 8));

            const float m_new = fmaxf(m_r[i], mm);
            const float corr  = __expf(m_r[i] - m_new);  // exp(-inf)=0 on first tile
            m_r[i] = m_new;

            float ls = 0.f;
#pragma unroll
            for (int j = 0; j < 4; j++) {
                float p = (s[i][j] == -INFINITY) ? 0.f : __expf(s[i][j] - m_new);
                s[i][j] = p;
                ls += p;
            }
            ls += __shfl_xor_sync(0xffffffffu, ls, 1);
            ls += __shfl_xor_sync(0xffffffffu, ls, 2);
            ls += __shfl_xor_sync(0xffffffffu, ls, 4);
            ls += __shfl_xor_sync(0xffffffffu, ls, 8);
            l_r[i] = l_r[i] * corr + ls;

#pragma unroll
            for (int j = 0; j < 8; j++) acc[i][j] *= corr;

            *(float4*)(sP + row * 64 + 4 * tx) =
                make_float4(s[i][0], s[i][1], s[i][2], s[i][3]);
        }
        __syncthreads();

        // O += P @ V : rows 4ty+i, cols 8tx..+7
#pragma unroll 4
        for (int k = 0; k < 64; k++) {
            float pp[4];
#pragma unroll
            for (int i = 0; i < 4; i++) pp[i] = sP[(4 * ty + i) * 64 + k];
            float vv[8];
            *(float4*)&vv[0] = *(float4*)(sV + k * 128 + 8 * tx);
            *(float4*)&vv[4] = *(float4*)(sV + k * 128 + 8 * tx + 4);
#pragma unroll
            for (int i = 0; i < 4; i++)
#pragma unroll
                for (int j = 0; j < 8; j++)
                    acc[i][j] += pp[i] * vv[j];
        }
    }

    // Normalize and write out to g_A (same [B,T,D] layout as Q)
    float* outp = g_A + (size_t)(b * Tn + q0) * Dn + h * HD;
#pragma unroll
    for (int i = 0; i < 4; i++) {
        const float inv = 1.f / l_r[i];
        float* op = outp + (size_t)(4 * ty + i) * Dn + 8 * tx;
        *(float4*)(op)     = make_float4(acc[i][0] * inv, acc[i][1] * inv,
                                         acc[i][2] * inv, acc[i][3] * inv);
        *(float4*)(op + 4) = make_float4(acc[i][4] * inv, acc[i][5] * inv,
                                         acc[i][6] * inv, acc[i][7] * inv);
    }
}

// ---------------------------------------------------------------------------
// Launch: Q/K/V projections -> flash attention -> output projection
// ---------------------------------------------------------------------------
extern "C" void kernel_launch(void* const* d_in, const int* in_sizes, int n_in,
                              void* d_out, int out_size)
{
    const float* x  = (const float*)d_in[0];
    const float* Wq = (const float*)d_in[1];
    const float* Wk = (const float*)d_in[2];
    const float* Wv = (const float*)d_in[3];
    const float* Wo = (const float*)d_in[4];
    float* out = (float*)d_out;

    float *pQ, *pK, *pV, *pA;
    cudaGetSymbolAddress((void**)&pQ, g_Q);
    cudaGetSymbolAddress((void**)&pK, g_K);
    cudaGetSymbolAddress((void**)&pV, g_V);
    cudaGetSymbolAddress((void**)&pA, g_A);

    cudaFuncSetAttribute(attn_kernel,
                         cudaFuncAttributeMaxDynamicSharedMemorySize, ATTN_SMEM);

    dim3 blk(256);
    // Projections
    sgemm128<<<dim3(Dn / 128, MROWS / 128), blk>>>(x, Wq, pQ, MROWS, Dn, Dn);
    sgemm128<<<dim3(DKV / 128, MROWS / 128), blk>>>(x, Wk, pK, MROWS, DKV, Dn);
    sgemm128<<<dim3(DKV / 128, MROWS / 128), blk>>>(x, Wv, pV, MROWS, DKV, Dn);
    // Attention
    attn_kernel<<<dim3(Tn / 64, Bn * Hn), blk, ATTN_SMEM>>>();
    // Output projection
    sgemm128<<<dim3(Dn / 128, MROWS / 128), blk>>>(pA, Wo, out, MROWS, Dn, Dn);
}

// round 3
// speedup vs baseline: 1.3831x; 1.3831x over previous
#include <cuda_runtime.h>
#include <cuda_bf16.h>
#include <math.h>
#include <stdint.h>

// Problem constants
#define Bn   2
#define Tn   2048
#define Dn   2048
#define Hn   16
#define Gn   4
#define HD   128
#define DKV  512
#define MROWS (Bn * Tn)   // 4096

// ---------------------------------------------------------------------------
// Scratch (allocation-free: __device__ globals)
// ---------------------------------------------------------------------------
__device__ float g_Q[(size_t)MROWS * Dn];   // 32 MB
__device__ float g_K[(size_t)MROWS * DKV];  // 8 MB
__device__ float g_V[(size_t)MROWS * DKV];  // 8 MB
__device__ float g_A[(size_t)MROWS * Dn];   // 32 MB (attention output)

// bf16 split buffers
__device__ __nv_bfloat16 g_xh[(size_t)MROWS * Dn];
__device__ __nv_bfloat16 g_xl[(size_t)MROWS * Dn];
__device__ __nv_bfloat16 g_ah[(size_t)MROWS * Dn];
__device__ __nv_bfloat16 g_al[(size_t)MROWS * Dn];
__device__ __nv_bfloat16 g_wqh[(size_t)Dn * Dn];     // [N][K] transposed
__device__ __nv_bfloat16 g_wql[(size_t)Dn * Dn];
__device__ __nv_bfloat16 g_wkh[(size_t)DKV * Dn];
__device__ __nv_bfloat16 g_wkl[(size_t)DKV * Dn];
__device__ __nv_bfloat16 g_wvh[(size_t)DKV * Dn];
__device__ __nv_bfloat16 g_wvl[(size_t)DKV * Dn];
__device__ __nv_bfloat16 g_woh[(size_t)Dn * Dn];
__device__ __nv_bfloat16 g_wol[(size_t)Dn * Dn];

// ---------------------------------------------------------------------------
// PTX helpers (compute_100-safe: cp.async + ldmatrix + mma.sync only)
// ---------------------------------------------------------------------------
__device__ __forceinline__ uint32_t s2u(const void* p) {
    uint32_t a;
    asm("{ .reg .u64 t; cvta.to.shared.u64 t, %1; cvt.u32.u64 %0, t; }"
        : "=r"(a) : "l"(p));
    return a;
}
__device__ __forceinline__ void cp16(uint32_t dst, const void* src) {
    asm volatile("cp.async.cg.shared.global [%0], [%1], 16;\n" :: "r"(dst), "l"(src));
}
#define CP_COMMIT() asm volatile("cp.async.commit_group;\n" ::: "memory")
#define CP_WAIT(n)  asm volatile("cp.async.wait_group %0;\n" :: "n"(n) : "memory")

__device__ __forceinline__ void ldsm4(uint32_t* r, uint32_t addr) {
    asm volatile("ldmatrix.sync.aligned.m8n8.x4.shared.b16 {%0,%1,%2,%3}, [%4];"
        : "=r"(r[0]), "=r"(r[1]), "=r"(r[2]), "=r"(r[3]) : "r"(addr));
}
__device__ __forceinline__ void mma16816(float* c, const uint32_t* a, const uint32_t* b) {
    asm volatile(
        "mma.sync.aligned.m16n8k16.row.col.f32.bf16.bf16.f32 "
        "{%0,%1,%2,%3}, {%4,%5,%6,%7}, {%8,%9}, {%0,%1,%2,%3};"
        : "+f"(c[0]), "+f"(c[1]), "+f"(c[2]), "+f"(c[3])
        : "r"(a[0]), "r"(a[1]), "r"(a[2]), "r"(a[3]), "r"(b[0]), "r"(b[1]));
}

// ---------------------------------------------------------------------------
// Prep kernels: fp32 -> (hi, lo) bf16 split; fused transpose+split for weights
// ---------------------------------------------------------------------------
__global__ void split_f32(const float* __restrict__ in,
                          __nv_bfloat16* __restrict__ hi,
                          __nv_bfloat16* __restrict__ lo, int n)
{
    int i = blockIdx.x * blockDim.x + threadIdx.x;
    if (i < n) {
        float v = in[i];
        __nv_bfloat16 h = __float2bfloat16(v);
        hi[i] = h;
        lo[i] = __float2bfloat16(v - __bfloat162float(h));
    }
}

// W [K][N] fp32 (row-major) -> Th/Tl [N][K] bf16 (K contiguous)
__global__ __launch_bounds__(256) void transpose_split(
    const float* __restrict__ W,
    __nv_bfloat16* __restrict__ Th, __nv_bfloat16* __restrict__ Tl,
    int K, int N)
{
    __shared__ float t[32][33];
    int n0 = blockIdx.x * 32, k0 = blockIdx.y * 32;
    int tx = threadIdx.x & 31, ty = threadIdx.x >> 5;   // 32 x 8
#pragma unroll
    for (int i = 0; i < 32; i += 8)
        t[ty + i][tx] = W[(size_t)(k0 + ty + i) * N + n0 + tx];
    __syncthreads();
#pragma unroll
    for (int i = 0; i < 32; i += 8) {
        float v = t[tx][ty + i];             // = W[k0+tx][n0+ty+i]
        __nv_bfloat16 h = __float2bfloat16(v);
        size_t o = (size_t)(n0 + ty + i) * K + k0 + tx;
        Th[o] = h;
        Tl[o] = __float2bfloat16(v - __bfloat162float(h));
    }
}

// ---------------------------------------------------------------------------
// mma.sync GEMM: C[M,N] fp32 = (Ah+Al)[M,K] @ (Bh+Bl)^T   (B stored [N][K])
// via Ah*Bh + Al*Bh + Ah*Bl. CTA 128x128, K-chunk 32, 3-stage cp.async.
// 256 threads = 8 warps (2 x 4); warp tile 64x32 (m frags 4, n frags 4).
// Smem tiles: 128 rows x 32 bf16, row stride 80 B (conflict-free ldmatrix).
// ---------------------------------------------------------------------------
#define KC        32
#define RSTRIDE   80
#define TILE_SB   (128 * RSTRIDE)            // 10240
#define STAGE_SB  (4 * TILE_SB)              // 40960 (Ah, Al, Bh, Bl)
#define NSTAGE    3
#define GEMM_SMEM (NSTAGE * STAGE_SB)        // 122880

__global__ __launch_bounds__(256) void gemm_tc(
    const __nv_bfloat16* __restrict__ Ah, const __nv_bfloat16* __restrict__ Al,
    const __nv_bfloat16* __restrict__ Bh, const __nv_bfloat16* __restrict__ Bl,
    float* __restrict__ C, int M, int N, int K)
{
    extern __shared__ char smem[];
    const uint32_t sb = s2u(smem);

    const int tid  = threadIdx.x;
    const int wid  = tid >> 5;
    const int lane = tid & 31;
    const int mw   = wid & 1;          // 0..1 -> warp row (64 rows)
    const int nw   = wid >> 1;         // 0..3 -> warp col (32 cols)
    const int row0 = blockIdx.y * 128;
    const int col0 = blockIdx.x * 128;
    const int NCHUNK = K / KC;

    const __nv_bfloat16* src[4] = {
        Ah + (size_t)row0 * K, Al + (size_t)row0 * K,
        Bh + (size_t)col0 * K, Bl + (size_t)col0 * K
    };

    // Prefetch one K-chunk (4 tiles of 128x32 bf16) into stage st
    auto prefetch = [&](int chunk, int st) {
        const int k0 = chunk * KC;
        const uint32_t stBase = sb + st * STAGE_SB;
#pragma unroll
        for (int arr = 0; arr < 4; arr++) {
            const uint32_t tb = stBase + arr * TILE_SB;
            const __nv_bfloat16* s = src[arr] + k0;
#pragma unroll
            for (int it = 0; it < 2; it++) {
                int cidx = tid + it * 256;     // 0..511
                int r = cidx >> 2;             // 0..127
                int c = cidx & 3;              // 0..3 (16B chunk)
                cp16(tb + r * RSTRIDE + c * 16, s + (size_t)r * K + c * 8);
            }
        }
        CP_COMMIT();
    };

    float acc[4][4][4];
#pragma unroll
    for (int i = 0; i < 4; i++)
#pragma unroll
        for (int j = 0; j < 4; j++)
#pragma unroll
            for (int v = 0; v < 4; v++) acc[i][j][v] = 0.f;

    prefetch(0, 0);
    if (NCHUNK > 1) prefetch(1, 1);

    // ldmatrix lane-address components
    const int a_lrow = lane & 15;                       // row within m16
    const int a_lcol = (lane >> 4) * 16;                // 16B chunk
    const int b_lrow = (lane & 7) + ((lane >> 4) << 3); // row within n16
    const int b_lcol = ((lane >> 3) & 1) * 16;

    for (int c = 0; c < NCHUNK; c++) {
        const int st = c % NSTAGE;
        if (c + 2 < NCHUNK) { prefetch(c + 2, (c + 2) % NSTAGE); CP_WAIT(2); }
        else if (c + 1 < NCHUNK) CP_WAIT(1);
        else CP_WAIT(0);
        __syncthreads();

        const uint32_t base = sb + st * STAGE_SB;
        const uint32_t tAh = base;
        const uint32_t tAl = base + TILE_SB;
        const uint32_t tBh = base + 2 * TILE_SB;
        const uint32_t tBl = base + 3 * TILE_SB;

#pragma unroll
        for (int ks = 0; ks < 2; ks++) {
            const int kb = ks * 32;     // byte offset of this k16 within the row

            // B fragments: 2 ldmatrix.x4 each for hi/lo -> 4 n-frags of 2 regs
            uint32_t bh[2][4], bl[2][4];
#pragma unroll
            for (int half = 0; half < 2; half++) {
                int n0 = nw * 32 + half * 16;
                uint32_t ba = (uint32_t)((n0 + b_lrow) * RSTRIDE + kb + b_lcol);
                ldsm4(bh[half], tBh + ba);
                ldsm4(bl[half], tBl + ba);
            }
            // A fragments: 4 ldmatrix.x4 each for hi/lo
            uint32_t ah[4][4], al[4][4];
#pragma unroll
            for (int mi = 0; mi < 4; mi++) {
                int m0 = mw * 64 + mi * 16;
                uint32_t aa = (uint32_t)((m0 + a_lrow) * RSTRIDE + kb + a_lcol);
                ldsm4(ah[mi], tAh + aa);
                ldsm4(al[mi], tAl + aa);
            }

#pragma unroll
            for (int mi = 0; mi < 4; mi++)
#pragma unroll
                for (int ni = 0; ni < 4; ni++) {
                    const uint32_t* bfh = &bh[ni >> 1][(ni & 1) * 2];
                    mma16816(acc[mi][ni], ah[mi], bfh);
                }
#pragma unroll
            for (int mi = 0; mi < 4; mi++)
#pragma unroll
                for (int ni = 0; ni < 4; ni++) {
                    const uint32_t* bfh = &bh[ni >> 1][(ni & 1) * 2];
                    mma16816(acc[mi][ni], al[mi], bfh);
                }
#pragma unroll
            for (int mi = 0; mi < 4; mi++)
#pragma unroll
                for (int ni = 0; ni < 4; ni++) {
                    const uint32_t* bfl = &bl[ni >> 1][(ni & 1) * 2];
                    mma16816(acc[mi][ni], ah[mi], bfl);
                }
        }
        __syncthreads();   // all warps done with stage st before it is refilled
    }

    // Epilogue: write accumulators
    const int mbase = row0 + mw * 64;
    const int nbase = col0 + nw * 32;
    const int tr = lane >> 2;
    const int tc = (lane & 3) * 2;
#pragma unroll
    for (int mi = 0; mi < 4; mi++)
#pragma unroll
        for (int ni = 0; ni < 4; ni++) {
            float* p0 = C + (size_t)(mbase + mi * 16 + tr) * N + nbase + ni * 8 + tc;
            *(float2*)p0 = make_float2(acc[mi][ni][0], acc[mi][ni][1]);
            float* p1 = p0 + (size_t)8 * N;
            *(float2*)p1 = make_float2(acc[mi][ni][2], acc[mi][ni][3]);
        }
}

// ---------------------------------------------------------------------------
// Flash attention (causal, GQA), fp32, online softmax.  (unchanged, known-good)
// ---------------------------------------------------------------------------
#define ATTN_SMEM ((64*128 + 64*132 + 64*128 + 64*64) * 4)   // 115712 B

__global__ __launch_bounds__(256) void attn_kernel()
{
    extern __shared__ float sm[];
    float* sQ = sm;                    // 8192
    float* sK = sQ + 64 * 128;         // 8448 (padded rows of 132)
    float* sV = sK + 64 * 132;         // 8192
    float* sP = sV + 64 * 128;         // 4096

    const int qt  = blockIdx.x;
    const int bh  = blockIdx.y;
    const int b   = bh >> 4;
    const int h   = bh & 15;
    const int g   = h >> 2;
    const int tid = threadIdx.x;
    const int tx  = tid & 15;
    const int ty  = tid >> 4;
    const int q0  = qt * 64;
    const float scale = 0.08838834764831843f;  // 1/sqrt(128)

    {
        const float* qsrc = g_Q + (size_t)(b * Tn + q0) * Dn + h * HD;
#pragma unroll
        for (int i = 0; i < 8; i++) {
            int idx = tid + i * 256;
            int r  = idx >> 5;
            int c4 = idx & 31;
            float4 v = *(const float4*)(qsrc + (size_t)r * Dn + c4 * 4);
            v.x *= scale; v.y *= scale; v.z *= scale; v.w *= scale;
            *(float4*)(sQ + r * 128 + c4 * 4) = v;
        }
    }

    float m_r[4], l_r[4], acc[4][8];
#pragma unroll
    for (int i = 0; i < 4; i++) {
        m_r[i] = -INFINITY; l_r[i] = 0.f;
#pragma unroll
        for (int j = 0; j < 8; j++) acc[i][j] = 0.f;
    }

    const float* ksrc0 = g_K + (size_t)(b * Tn) * DKV + g * HD;
    const float* vsrc0 = g_V + (size_t)(b * Tn) * DKV + g * HD;

    for (int kt = 0; kt <= qt; kt++) {
        __syncthreads();

        {
            const float* ks = ksrc0 + (size_t)(kt * 64) * DKV;
            const float* vs = vsrc0 + (size_t)(kt * 64) * DKV;
#pragma unroll
            for (int i = 0; i < 8; i++) {
                int idx = tid + i * 256;
                int r  = idx >> 5;
                int c4 = idx & 31;
                *(float4*)(sK + r * 132 + c4 * 4) =
                    *(const float4*)(ks + (size_t)r * DKV + c4 * 4);
                *(float4*)(sV + r * 128 + c4 * 4) =
                    *(const float4*)(vs + (size_t)r * DKV + c4 * 4);
            }
        }
        __syncthreads();

        float s[4][4];
#pragma unroll
        for (int i = 0; i < 4; i++)
#pragma unroll
            for (int j = 0; j < 4; j++) s[i][j] = 0.f;

#pragma unroll 8
        for (int d4 = 0; d4 < 128; d4 += 4) {
            float4 a[4], bv[4];
#pragma unroll
            for (int i = 0; i < 4; i++)
                a[i] = *(float4*)(sQ + (4 * ty + i) * 128 + d4);
#pragma unroll
            for (int j = 0; j < 4; j++)
                bv[j] = *(float4*)(sK + (4 * tx + j) * 132 + d4);
#pragma unroll
            for (int i = 0; i < 4; i++)
#pragma unroll
                for (int j = 0; j < 4; j++)
                    s[i][j] += a[i].x * bv[j].x + a[i].y * bv[j].y
                             + a[i].z * bv[j].z + a[i].w * bv[j].w;
        }

        const bool diag = (kt == qt);

#pragma unroll
        for (int i = 0; i < 4; i++) {
            const int row = 4 * ty + i;
            if (diag) {
#pragma unroll
                for (int j = 0; j < 4; j++)
                    if (4 * tx + j > row) s[i][j] = -INFINITY;
            }
            float mm = fmaxf(fmaxf(s[i][0], s[i][1]), fmaxf(s[i][2], s[i][3]));
            mm = fmaxf(mm, __shfl_xor_sync(0xffffffffu, mm, 1));
            mm = fmaxf(mm, __shfl_xor_sync(0xffffffffu, mm, 2));
            mm = fmaxf(mm, __shfl_xor_sync(0xffffffffu, mm, 4));
            mm = fmaxf(mm, __shfl_xor_sync(0xffffffffu, mm, 8));

            const float m_new = fmaxf(m_r[i], mm);
            const float corr  = __expf(m_r[i] - m_new);
            m_r[i] = m_new;

            float ls = 0.f;
#pragma unroll
            for (int j = 0; j < 4; j++) {
                float p = (s[i][j] == -INFINITY) ? 0.f : __expf(s[i][j] - m_new);
                s[i][j] = p;
                ls += p;
            }
            ls += __shfl_xor_sync(0xffffffffu, ls, 1);
            ls += __shfl_xor_sync(0xffffffffu, ls, 2);
            ls += __shfl_xor_sync(0xffffffffu, ls, 4);
            ls += __shfl_xor_sync(0xffffffffu, ls, 8);
            l_r[i] = l_r[i] * corr + ls;

#pragma unroll
            for (int j = 0; j < 8; j++) acc[i][j] *= corr;

            *(float4*)(sP + row * 64 + 4 * tx) =
                make_float4(s[i][0], s[i][1], s[i][2], s[i][3]);
        }
        __syncthreads();

#pragma unroll 4
        for (int k = 0; k < 64; k++) {
            float pp[4];
#pragma unroll
            for (int i = 0; i < 4; i++) pp[i] = sP[(4 * ty + i) * 64 + k];
            float vv[8];
            *(float4*)&vv[0] = *(float4*)(sV + k * 128 + 8 * tx);
            *(float4*)&vv[4] = *(float4*)(sV + k * 128 + 8 * tx + 4);
#pragma unroll
            for (int i = 0; i < 4; i++)
#pragma unroll
                for (int j = 0; j < 8; j++)
                    acc[i][j] += pp[i] * vv[j];
        }
    }

    float* outp = g_A + (size_t)(b * Tn + q0) * Dn + h * HD;
#pragma unroll
    for (int i = 0; i < 4; i++) {
        const float inv = 1.f / l_r[i];
        float* op = outp + (size_t)(4 * ty + i) * Dn + 8 * tx;
        *(float4*)(op)     = make_float4(acc[i][0] * inv, acc[i][1] * inv,
                                         acc[i][2] * inv, acc[i][3] * inv);
        *(float4*)(op + 4) = make_float4(acc[i][4] * inv, acc[i][5] * inv,
                                         acc[i][6] * inv, acc[i][7] * inv);
    }
}

// ---------------------------------------------------------------------------
// Launch
// ---------------------------------------------------------------------------
extern "C" void kernel_launch(void* const* d_in, const int* in_sizes, int n_in,
                              void* d_out, int out_size)
{
    const float* x  = (const float*)d_in[0];
    const float* Wq = (const float*)d_in[1];
    const float* Wk = (const float*)d_in[2];
    const float* Wv = (const float*)d_in[3];
    const float* Wo = (const float*)d_in[4];
    float* out = (float*)d_out;

    float *pQ, *pK, *pV, *pA;
    cudaGetSymbolAddress((void**)&pQ, g_Q);
    cudaGetSymbolAddress((void**)&pK, g_K);
    cudaGetSymbolAddress((void**)&pV, g_V);
    cudaGetSymbolAddress((void**)&pA, g_A);
    __nv_bfloat16 *xh, *xl, *ah, *al, *wqh, *wql, *wkh, *wkl, *wvh, *wvl, *woh, *wol;
    cudaGetSymbolAddress((void**)&xh,  g_xh);
    cudaGetSymbolAddress((void**)&xl,  g_xl);
    cudaGetSymbolAddress((void**)&ah,  g_ah);
    cudaGetSymbolAddress((void**)&al,  g_al);
    cudaGetSymbolAddress((void**)&wqh, g_wqh);
    cudaGetSymbolAddress((void**)&wql, g_wql);
    cudaGetSymbolAddress((void**)&wkh, g_wkh);
    cudaGetSymbolAddress((void**)&wkl, g_wkl);
    cudaGetSymbolAddress((void**)&wvh, g_wvh);
    cudaGetSymbolAddress((void**)&wvl, g_wvl);
    cudaGetSymbolAddress((void**)&woh, g_woh);
    cudaGetSymbolAddress((void**)&wol, g_wol);

    cudaFuncSetAttribute(attn_kernel,
                         cudaFuncAttributeMaxDynamicSharedMemorySize, ATTN_SMEM);
    cudaFuncSetAttribute(gemm_tc,
                         cudaFuncAttributeMaxDynamicSharedMemorySize, GEMM_SMEM);

    const int nX = MROWS * Dn;

    // Split inputs / weights to bf16 hi/lo
    split_f32<<<(nX + 255) / 256, 256>>>(x, xh, xl, nX);
    transpose_split<<<dim3(Dn / 32, Dn / 32), 256>>>(Wq, wqh, wql, Dn, Dn);
    transpose_split<<<dim3(DKV / 32, Dn / 32), 256>>>(Wk, wkh, wkl, Dn, DKV);
    transpose_split<<<dim3(DKV / 32, Dn / 32), 256>>>(Wv, wvh, wvl, Dn, DKV);
    transpose_split<<<dim3(Dn / 32, Dn / 32), 256>>>(Wo, woh, wol, Dn, Dn);

    // Projections on tensor cores (mma.sync)
    gemm_tc<<<dim3(Dn / 128, MROWS / 128), 256, GEMM_SMEM>>>(
        xh, xl, wqh, wql, pQ, MROWS, Dn, Dn);
    gemm_tc<<<dim3(DKV / 128, MROWS / 128), 256, GEMM_SMEM>>>(
        xh, xl, wkh, wkl, pK, MROWS, DKV, Dn);
    gemm_tc<<<dim3(DKV / 128, MROWS / 128), 256, GEMM_SMEM>>>(
        xh, xl, wvh, wvl, pV, MROWS, DKV, Dn);

    // Attention (fp32 SIMT)
    attn_kernel<<<dim3(Tn / 64, Bn * Hn), 256, ATTN_SMEM>>>();

    // Output projection
    split_f32<<<(nX + 255) / 256, 256>>>(pA, ah, al, nX);
    gemm_tc<<<dim3(Dn / 128, MROWS / 128), 256, GEMM_SMEM>>>(
        ah, al, woh, wol, out, MROWS, Dn, Dn);
}